// round 14
// baseline (speedup 1.0000x reference)
#include <cuda_runtime.h>
#include <cuda_fp16.h>
#include <cstdint>

#define NB 16
#define NT 2048
#define HD 64

// fp16 Q/K/V scratch (Q pre-scaled); device globals per allocation-free rule
__device__ uint32_t g_Qh[NB * NT * 32];
__device__ uint32_t g_Kh[NB * NT * 32];
__device__ uint32_t g_Vh[NB * NT * 32];

// ---------------------------------------------------------------------------
// helpers
// ---------------------------------------------------------------------------
__device__ __forceinline__ uint32_t smem_u32(const void* p) {
    uint32_t a;
    asm("{ .reg .u64 t; cvta.to.shared.u64 t, %1; cvt.u32.u64 %0, t; }"
        : "=r"(a) : "l"(p));
    return a;
}
__device__ __forceinline__ float ex2(float x) {
    float y;
    asm("ex2.approx.ftz.f32 %0, %1;" : "=f"(y) : "f"(x));
    return y;
}
__device__ __forceinline__ uint32_t pack_h2(float a, float b) {
    __half2 h = __floats2half2_rn(a, b);
    return *reinterpret_cast<uint32_t*>(&h);
}
// m16n8k16 fp16 mma, fp32 accumulate (arch-neutral PTX; HMMA on sm_103)
__device__ __forceinline__ void mma16(float c[4], const uint32_t a[4],
                                      uint32_t b0, uint32_t b1) {
    asm volatile(
        "mma.sync.aligned.m16n8k16.row.col.f32.f16.f16.f32 "
        "{%0,%1,%2,%3}, {%4,%5,%6,%7}, {%8,%9}, {%0,%1,%2,%3};"
        : "+f"(c[0]), "+f"(c[1]), "+f"(c[2]), "+f"(c[3])
        : "r"(a[0]), "r"(a[1]), "r"(a[2]), "r"(a[3]), "r"(b0), "r"(b1));
}
__device__ __forceinline__ void ldsm4(uint32_t& r0, uint32_t& r1, uint32_t& r2,
                                      uint32_t& r3, uint32_t addr) {
    asm volatile("ldmatrix.sync.aligned.m8n8.x4.shared.b16 {%0,%1,%2,%3}, [%4];"
                 : "=r"(r0), "=r"(r1), "=r"(r2), "=r"(r3) : "r"(addr));
}
__device__ __forceinline__ void ldsm4t(uint32_t& r0, uint32_t& r1, uint32_t& r2,
                                       uint32_t& r3, uint32_t addr) {
    asm volatile("ldmatrix.sync.aligned.m8n8.x4.trans.shared.b16 {%0,%1,%2,%3}, [%4];"
                 : "=r"(r0), "=r"(r1), "=r"(r2), "=r"(r3) : "r"(addr));
}
__device__ __forceinline__ void cp16(uint32_t dst, const void* src) {
    asm volatile("cp.async.cg.shared.global [%0], [%1], 16;"
                 :: "r"(dst), "l"(__cvta_generic_to_global(src)) : "memory");
}
__device__ __forceinline__ void cp_commit() {
    asm volatile("cp.async.commit_group;" ::: "memory");
}
template <int N>
__device__ __forceinline__ void cp_wait() {
    asm volatile("cp.async.wait_group %0;" :: "n"(N) : "memory");
}

// ---------------------------------------------------------------------------
// Kernel 1: QKV via fp16 mma, 2-term compensation (xh*Wh + xl*Wh).
// (xh*Wl dropped: fp16 storage rounding of Q/K/V dominates anyway.)
// Outputs fp16, Q pre-scaled by 0.125*log2e. 256 CTAs x 128 rows.
// smem: Wh[3][64][72]h @0 (27648 B). Pitch 144B (ldmatrix conflict-free).
// ---------------------------------------------------------------------------
#define QKV_SMEM 27648

__global__ __launch_bounds__(256, 2) void qkv_kernel(
    const float* __restrict__ x, const float* __restrict__ Wq,
    const float* __restrict__ Wk, const float* __restrict__ Wv)
{
    extern __shared__ char sm[];
    const uint32_t sbase = smem_u32(sm);
    const int tid = threadIdx.x, lane = tid & 31;
    const int g = lane >> 2, t = lane & 3;
    const int m0 = (tid >> 5) * 16;
    const int row0 = blockIdx.x * 128;
    const float qsc = 0.125f * 1.4426950408889634f;

    // W -> smem (fp16 hi only)
    for (int idx = tid; idx < 3 * 64 * 16; idx += 256) {
        int m = idx >> 10, r = (idx >> 4) & 63, c4 = (idx & 15) << 2;
        const float* W = (m == 0) ? Wq : (m == 1) ? Wk : Wv;
        float4 v = *(const float4*)(W + r * 64 + c4);
        *(uint2*)(sm + m * 9216 + r * 144 + c4 * 2) =
            make_uint2(pack_h2(v.x, v.y), pack_h2(v.z, v.w));
    }

    // A fragments (x hi/lo) straight from gmem
    uint32_t ah[4][4], al[4][4];
    {
        const float* xp = x + (size_t)row0 * 64;
        #pragma unroll
        for (int kc = 0; kc < 4; kc++) {
            const int r0 = m0 + g, r1 = r0 + 8;
            const int c0 = 16 * kc + 2 * t, c1 = c0 + 8;
            const int rr[4] = {r0, r1, r0, r1};
            const int cc[4] = {c0, c0, c1, c1};
            #pragma unroll
            for (int j = 0; j < 4; j++) {
                float2 v = *(const float2*)(xp + rr[j] * 64 + cc[j]);
                uint32_t hi = pack_h2(v.x, v.y);
                float2 bk = __half22float2(*(__half2*)&hi);
                ah[kc][j] = hi;
                al[kc][j] = pack_h2(v.x - bk.x, v.y - bk.y);
            }
        }
    }
    __syncthreads();

    const uint32_t aW = sbase + ((lane & 7) + ((lane >> 4) << 3)) * 144 +
                        ((lane >> 3) & 1) * 16;
    #pragma unroll
    for (int m = 0; m < 3; m++) {
        float acc[8][4];
        #pragma unroll
        for (int nb = 0; nb < 8; nb++)
            #pragma unroll
            for (int e = 0; e < 4; e++) acc[nb][e] = 0.f;

        #pragma unroll
        for (int kc = 0; kc < 4; kc++) {
            #pragma unroll
            for (int nbp = 0; nbp < 4; nbp++) {
                uint32_t h0, h1, h2, h3;
                ldsm4(h0, h1, h2, h3, aW + m * 9216 + nbp * 16 * 144 + kc * 32);
                mma16(acc[2 * nbp],     ah[kc], h0, h1);
                mma16(acc[2 * nbp],     al[kc], h0, h1);
                mma16(acc[2 * nbp + 1], ah[kc], h2, h3);
                mma16(acc[2 * nbp + 1], al[kc], h2, h3);
            }
        }

        uint32_t* dst = (m == 0) ? g_Qh : (m == 1) ? g_Kh : g_Vh;
        const float s = (m == 0) ? qsc : 1.0f;
        #pragma unroll
        for (int nb = 0; nb < 8; nb++) {
            dst[(size_t)(row0 + m0 + g) * 32 + 4 * nb + t] =
                pack_h2(acc[nb][0] * s, acc[nb][1] * s);
            dst[(size_t)(row0 + m0 + g + 8) * 32 + 4 * nb + t] =
                pack_h2(acc[nb][2] * s, acc[nb][3] * s);
        }
    }
}

// ---------------------------------------------------------------------------
// CTA schedule (validated): singles get the 40 heaviest units, pairs are
// complementary -> max SM load ~16 tile-units.
// ---------------------------------------------------------------------------
__device__ __forceinline__ void sched(int bid, int& b, int& qi) {
    if (bid >= 108 && bid < 148) {
        int k = bid - 108;
        if (k < 32) { qi = 15 - (k >> 4); b = k & 15; }
        else        { qi = 13;            b = k - 32; }
    } else {
        int j = (bid < 108) ? bid : (363 - bid);
        if (j < 8) { qi = 13; b = 8 + j; }
        else       { qi = 12 - ((j - 8) >> 4); b = (j - 8) & 15; }
    }
}

// ---------------------------------------------------------------------------
// Kernel 2: fp16 mma.sync causal flash attention, cp.async double-buffered,
// cross-half interleaving: S0 -> softmax0 -> [PV0 (x) S1] -> softmax1 -> PV1.
// 256 threads / 8 warps; warp owns 16 q-rows; tile 128q x 128k.
// smem: K0@0 K1@18432 V0@36864 V1@55296 (each 128x72h), Ps[8][16][72]h @73728.
// ---------------------------------------------------------------------------
#define ATTN_SMEM 92160

__device__ __forceinline__ void load_kv(uint32_t sK, uint32_t sV,
                                        const uint32_t* Kg, const uint32_t* Vg,
                                        int tid) {
    #pragma unroll
    for (int p = 0; p < 4; p++) {
        int idx = tid + p * 256;          // 0..1023
        int row = idx >> 3, ch = idx & 7;
        cp16(sK + row * 144 + ch * 16, (const char*)Kg + row * 128 + ch * 16);
        cp16(sV + row * 144 + ch * 16, (const char*)Vg + row * 128 + ch * 16);
    }
}

__global__ __launch_bounds__(256, 2) void attn_kernel(float* __restrict__ out)
{
    extern __shared__ char sm[];
    const uint32_t sbase = smem_u32(sm);
    const int tid  = threadIdx.x;
    const int lane = tid & 31;
    const int g    = lane >> 2;
    const int t    = lane & 3;
    const int w    = tid >> 5;
    const int m0   = w * 16;
    int b, qi;
    sched((int)blockIdx.x, b, qi);
    const int qt0 = qi << 7;

    // kick off tile 0 loads immediately
    load_kv(sbase, sbase + 36864,
            g_Kh + (size_t)(b * NT + 0) * 32,
            g_Vh + (size_t)(b * NT + 0) * 32, tid);
    cp_commit();

    // ldmatrix per-lane base addresses (add cur*18432 for buffer)
    const uint32_t aK = sbase + ((lane & 7) + ((lane >> 4) << 3)) * 144 +
                        ((lane >> 3) & 1) * 16;
    const uint32_t aV = sbase + 36864 + (lane & 15) * 144 + (lane >> 4) * 16;
    const uint32_t aP = sbase + 73728 + w * 2304 + (lane & 15) * 144 +
                        (lane >> 4) * 16;
    __half2* PsW = (__half2*)(sm + 73728 + w * 2304);

    // Q A-fragments (already fp16 + pre-scaled in gmem)
    uint32_t qf[4][4];
    {
        const uint32_t* Qg = g_Qh + (size_t)(b * NT + qt0) * 32;
        const int r0 = m0 + g, r1 = r0 + 8;
        #pragma unroll
        for (int kc = 0; kc < 4; kc++) {
            qf[kc][0] = Qg[r0 * 32 + 8 * kc + t];
            qf[kc][1] = Qg[r1 * 32 + 8 * kc + t];
            qf[kc][2] = Qg[r0 * 32 + 8 * kc + t + 4];
            qf[kc][3] = Qg[r1 * 32 + 8 * kc + t + 4];
        }
    }

    float oacc[8][4];
    #pragma unroll
    for (int hb = 0; hb < 8; hb++)
        #pragma unroll
        for (int e = 0; e < 4; e++) oacc[hb][e] = 0.f;
    float l0 = 0.f, l1 = 0.f, l0b = 0.f, l1b = 0.f;
    const int r0 = m0 + g, r1 = r0 + 8;

    for (int kt = 0; kt <= qi; ++kt) {
        const int cur = kt & 1;
        // prefetch next tile into the other buffer (overlaps compute below)
        if (kt < qi) {
            load_kv(sbase + (cur ^ 1) * 18432, sbase + 36864 + (cur ^ 1) * 18432,
                    g_Kh + (size_t)(b * NT + ((kt + 1) << 7)) * 32,
                    g_Vh + (size_t)(b * NT + ((kt + 1) << 7)) * 32, tid);
            cp_commit();
            cp_wait<1>();
        } else {
            cp_wait<0>();
        }
        __syncthreads();   // tile kt data visible to all warps

        const uint32_t aKc = aK + cur * 18432;
        const uint32_t aVc = aV + cur * 18432;
        const bool diag  = (kt == qi);
        const bool skip1 = diag && (m0 < 64);   // upper half fully masked

        // ---- S over keys [0,64) ----
        float sacc[8][4];
        #pragma unroll
        for (int nb = 0; nb < 8; nb++)
            #pragma unroll
            for (int e = 0; e < 4; e++) sacc[nb][e] = 0.f;
        #pragma unroll
        for (int kc = 0; kc < 4; kc++) {
            #pragma unroll
            for (int nbp = 0; nbp < 4; nbp++) {
                uint32_t b0, b1, b2, b3;
                ldsm4(b0, b1, b2, b3, aKc + (16 * nbp) * 144 + kc * 32);
                mma16(sacc[2 * nbp],     qf[kc], b0, b1);
                mma16(sacc[2 * nbp + 1], qf[kc], b2, b3);
            }
        }

        // ---- softmax h=0 -> Ps ----
        __syncwarp();
        #pragma unroll
        for (int nb = 0; nb < 8; nb++) {
            const int c0 = 8 * nb + 2 * t;
            float e0 = ex2(sacc[nb][0]);
            float e1 = ex2(sacc[nb][1]);
            float e2 = ex2(sacc[nb][2]);
            float e3 = ex2(sacc[nb][3]);
            if (diag) {
                if (c0     > r0) e0 = 0.f;
                if (c0 + 1 > r0) e1 = 0.f;
                if (c0     > r1) e2 = 0.f;
                if (c0 + 1 > r1) e3 = 0.f;
            }
            if (nb & 1) { l0b += e0 + e1; l1b += e2 + e3; }
            else        { l0  += e0 + e1; l1  += e2 + e3; }
            uint32_t p01 = pack_h2(e0, e1), p23 = pack_h2(e2, e3);
            PsW[g * 36 + 4 * nb + t]       = *(__half2*)&p01;
            PsW[(g + 8) * 36 + 4 * nb + t] = *(__half2*)&p23;
        }
        __syncwarp();

        // ---- interleaved: PV over [0,64)  (x)  S over [64,128) ----
        float sacc1[8][4];
        if (!skip1) {
            #pragma unroll
            for (int nb = 0; nb < 8; nb++)
                #pragma unroll
                for (int e = 0; e < 4; e++) sacc1[nb][e] = 0.f;
        }
        #pragma unroll
        for (int kc = 0; kc < 4; kc++) {
            uint32_t pa[4];
            ldsm4(pa[0], pa[1], pa[2], pa[3], aP + kc * 32);
            #pragma unroll
            for (int j = 0; j < 4; j++) {
                uint32_t v0, v1, v2, v3;
                ldsm4t(v0, v1, v2, v3, aVc + (16 * kc) * 144 + j * 32);
                if (!skip1) {
                    uint32_t k0, k1, k2, k3;
                    ldsm4(k0, k1, k2, k3,
                          aKc + (64 + 16 * j) * 144 + kc * 32);
                    mma16(oacc[2 * j],      pa, v0, v1);
                    mma16(sacc1[2 * j],     qf[kc], k0, k1);
                    mma16(oacc[2 * j + 1],  pa, v2, v3);
                    mma16(sacc1[2 * j + 1], qf[kc], k2, k3);
                } else {
                    mma16(oacc[2 * j],     pa, v0, v1);
                    mma16(oacc[2 * j + 1], pa, v2, v3);
                }
            }
        }

        if (!skip1) {
            // ---- softmax h=1 -> Ps ----
            __syncwarp();
            #pragma unroll
            for (int nb = 0; nb < 8; nb++) {
                const int c0 = 64 + 8 * nb + 2 * t;
                float e0 = ex2(sacc1[nb][0]);
                float e1 = ex2(sacc1[nb][1]);
                float e2 = ex2(sacc1[nb][2]);
                float e3 = ex2(sacc1[nb][3]);
                if (diag) {
                    if (c0     > r0) e0 = 0.f;
                    if (c0 + 1 > r0) e1 = 0.f;
                    if (c0     > r1) e2 = 0.f;
                    if (c0 + 1 > r1) e3 = 0.f;
                }
                if (nb & 1) { l0b += e0 + e1; l1b += e2 + e3; }
                else        { l0  += e0 + e1; l1  += e2 + e3; }
                uint32_t p01 = pack_h2(e0, e1), p23 = pack_h2(e2, e3);
                PsW[g * 36 + 4 * nb + t]       = *(__half2*)&p01;
                PsW[(g + 8) * 36 + 4 * nb + t] = *(__half2*)&p23;
            }
            __syncwarp();

            // ---- PV over [64,128) ----
            #pragma unroll
            for (int kc = 0; kc < 4; kc++) {
                uint32_t pa[4];
                ldsm4(pa[0], pa[1], pa[2], pa[3], aP + kc * 32);
                #pragma unroll
                for (int hbp = 0; hbp < 4; hbp++) {
                    uint32_t v0, v1, v2, v3;
                    ldsm4t(v0, v1, v2, v3,
                           aVc + (64 + 16 * kc) * 144 + hbp * 32);
                    mma16(oacc[2 * hbp],     pa, v0, v1);
                    mma16(oacc[2 * hbp + 1], pa, v2, v3);
                }
            }
        }
        __syncthreads();   // all warps done with buffer cur before refill
    }

    // ---- epilogue: reduce l across quad, normalize, store ----
    l0 += l0b; l1 += l1b;
    l0 += __shfl_xor_sync(0xffffffffu, l0, 1);
    l0 += __shfl_xor_sync(0xffffffffu, l0, 2);
    l1 += __shfl_xor_sync(0xffffffffu, l1, 1);
    l1 += __shfl_xor_sync(0xffffffffu, l1, 2);
    const float inv0 = 1.0f / l0;
    const float inv1 = 1.0f / l1;

    float* Og = out + (size_t)(b * NT + qt0) * HD;
    #pragma unroll
    for (int hb = 0; hb < 8; hb++) {
        int c0 = 8 * hb + 2 * t;
        *(float2*)(Og + (m0 + g) * 64 + c0) =
            make_float2(oacc[hb][0] * inv0, oacc[hb][1] * inv0);
        *(float2*)(Og + (m0 + g + 8) * 64 + c0) =
            make_float2(oacc[hb][2] * inv1, oacc[hb][3] * inv1);
    }
}

// ---------------------------------------------------------------------------
extern "C" void kernel_launch(void* const* d_in, const int* in_sizes, int n_in,
                              void* d_out, int out_size)
{
    const float* x  = (const float*)d_in[0];
    const float* Wq = (const float*)d_in[1];
    const float* Wk = (const float*)d_in[2];
    const float* Wv = (const float*)d_in[3];
    float* out = (float*)d_out;

    cudaFuncSetAttribute(qkv_kernel,  cudaFuncAttributeMaxDynamicSharedMemorySize, QKV_SMEM);
    cudaFuncSetAttribute(attn_kernel, cudaFuncAttributeMaxDynamicSharedMemorySize, ATTN_SMEM);

    qkv_kernel<<<(NB * NT) / 128, 256, QKV_SMEM>>>(x, Wq, Wk, Wv);
    attn_kernel<<<NB * (NT / 128), 256, ATTN_SMEM>>>(out);
}

// round 15
// speedup vs baseline: 1.6281x; 1.6281x over previous
#include <cuda_runtime.h>
#include <cuda_fp16.h>
#include <cstdint>

#define NB 16
#define NT 2048
#define HD 64

// fp16 Q/K/V scratch (Q pre-scaled); device globals per allocation-free rule
__device__ uint32_t g_Qh[NB * NT * 32];
__device__ uint32_t g_Kh[NB * NT * 32];
__device__ uint32_t g_Vh[NB * NT * 32];

// ---------------------------------------------------------------------------
// helpers
// ---------------------------------------------------------------------------
__device__ __forceinline__ uint32_t smem_u32(const void* p) {
    uint32_t a;
    asm("{ .reg .u64 t; cvta.to.shared.u64 t, %1; cvt.u32.u64 %0, t; }"
        : "=r"(a) : "l"(p));
    return a;
}
__device__ __forceinline__ float ex2(float x) {
    float y;
    asm("ex2.approx.ftz.f32 %0, %1;" : "=f"(y) : "f"(x));
    return y;
}
__device__ __forceinline__ uint32_t pack_h2(float a, float b) {
    __half2 h = __floats2half2_rn(a, b);
    return *reinterpret_cast<uint32_t*>(&h);
}
// m16n8k16 fp16 mma, fp32 accumulate (arch-neutral PTX; HMMA on sm_103)
__device__ __forceinline__ void mma16(float c[4], const uint32_t a[4],
                                      uint32_t b0, uint32_t b1) {
    asm volatile(
        "mma.sync.aligned.m16n8k16.row.col.f32.f16.f16.f32 "
        "{%0,%1,%2,%3}, {%4,%5,%6,%7}, {%8,%9}, {%0,%1,%2,%3};"
        : "+f"(c[0]), "+f"(c[1]), "+f"(c[2]), "+f"(c[3])
        : "r"(a[0]), "r"(a[1]), "r"(a[2]), "r"(a[3]), "r"(b0), "r"(b1));
}
__device__ __forceinline__ void ldsm4(uint32_t& r0, uint32_t& r1, uint32_t& r2,
                                      uint32_t& r3, uint32_t addr) {
    asm volatile("ldmatrix.sync.aligned.m8n8.x4.shared.b16 {%0,%1,%2,%3}, [%4];"
                 : "=r"(r0), "=r"(r1), "=r"(r2), "=r"(r3) : "r"(addr));
}
__device__ __forceinline__ void ldsm4t(uint32_t& r0, uint32_t& r1, uint32_t& r2,
                                       uint32_t& r3, uint32_t addr) {
    asm volatile("ldmatrix.sync.aligned.m8n8.x4.trans.shared.b16 {%0,%1,%2,%3}, [%4];"
                 : "=r"(r0), "=r"(r1), "=r"(r2), "=r"(r3) : "r"(addr));
}
__device__ __forceinline__ void cp16(uint32_t dst, const void* src) {
    asm volatile("cp.async.cg.shared.global [%0], [%1], 16;"
                 :: "r"(dst), "l"(__cvta_generic_to_global(src)) : "memory");
}
__device__ __forceinline__ void cp_commit() {
    asm volatile("cp.async.commit_group;" ::: "memory");
}
template <int N>
__device__ __forceinline__ void cp_wait() {
    asm volatile("cp.async.wait_group %0;" :: "n"(N) : "memory");
}

// ---------------------------------------------------------------------------
// Kernel 1: QKV via fp16 mma, 2-term compensation (xh*Wh + xl*Wh).
// (validated R13: rel_err 3.7e-4.) Outputs fp16, Q pre-scaled by 0.125*log2e.
// smem: Wh[3][64][72]h @0 (27648 B). Pitch 144B (ldmatrix conflict-free).
// ---------------------------------------------------------------------------
#define QKV_SMEM 27648

__global__ __launch_bounds__(256, 2) void qkv_kernel(
    const float* __restrict__ x, const float* __restrict__ Wq,
    const float* __restrict__ Wk, const float* __restrict__ Wv)
{
    extern __shared__ char sm[];
    const uint32_t sbase = smem_u32(sm);
    const int tid = threadIdx.x, lane = tid & 31;
    const int g = lane >> 2, t = lane & 3;
    const int m0 = (tid >> 5) * 16;
    const int row0 = blockIdx.x * 128;
    const float qsc = 0.125f * 1.4426950408889634f;

    // W -> smem (fp16 hi only)
    for (int idx = tid; idx < 3 * 64 * 16; idx += 256) {
        int m = idx >> 10, r = (idx >> 4) & 63, c4 = (idx & 15) << 2;
        const float* W = (m == 0) ? Wq : (m == 1) ? Wk : Wv;
        float4 v = *(const float4*)(W + r * 64 + c4);
        *(uint2*)(sm + m * 9216 + r * 144 + c4 * 2) =
            make_uint2(pack_h2(v.x, v.y), pack_h2(v.z, v.w));
    }

    // A fragments (x hi/lo) straight from gmem
    uint32_t ah[4][4], al[4][4];
    {
        const float* xp = x + (size_t)row0 * 64;
        #pragma unroll
        for (int kc = 0; kc < 4; kc++) {
            const int r0 = m0 + g, r1 = r0 + 8;
            const int c0 = 16 * kc + 2 * t, c1 = c0 + 8;
            const int rr[4] = {r0, r1, r0, r1};
            const int cc[4] = {c0, c0, c1, c1};
            #pragma unroll
            for (int j = 0; j < 4; j++) {
                float2 v = *(const float2*)(xp + rr[j] * 64 + cc[j]);
                uint32_t hi = pack_h2(v.x, v.y);
                float2 bk = __half22float2(*(__half2*)&hi);
                ah[kc][j] = hi;
                al[kc][j] = pack_h2(v.x - bk.x, v.y - bk.y);
            }
        }
    }
    __syncthreads();

    const uint32_t aW = sbase + ((lane & 7) + ((lane >> 4) << 3)) * 144 +
                        ((lane >> 3) & 1) * 16;
    #pragma unroll
    for (int m = 0; m < 3; m++) {
        float acc[8][4];
        #pragma unroll
        for (int nb = 0; nb < 8; nb++)
            #pragma unroll
            for (int e = 0; e < 4; e++) acc[nb][e] = 0.f;

        #pragma unroll
        for (int kc = 0; kc < 4; kc++) {
            #pragma unroll
            for (int nbp = 0; nbp < 4; nbp++) {
                uint32_t h0, h1, h2, h3;
                ldsm4(h0, h1, h2, h3, aW + m * 9216 + nbp * 16 * 144 + kc * 32);
                mma16(acc[2 * nbp],     ah[kc], h0, h1);
                mma16(acc[2 * nbp],     al[kc], h0, h1);
                mma16(acc[2 * nbp + 1], ah[kc], h2, h3);
                mma16(acc[2 * nbp + 1], al[kc], h2, h3);
            }
        }

        uint32_t* dst = (m == 0) ? g_Qh : (m == 1) ? g_Kh : g_Vh;
        const float s = (m == 0) ? qsc : 1.0f;
        #pragma unroll
        for (int nb = 0; nb < 8; nb++) {
            dst[(size_t)(row0 + m0 + g) * 32 + 4 * nb + t] =
                pack_h2(acc[nb][0] * s, acc[nb][1] * s);
            dst[(size_t)(row0 + m0 + g + 8) * 32 + 4 * nb + t] =
                pack_h2(acc[nb][2] * s, acc[nb][3] * s);
        }
    }
}

// ---------------------------------------------------------------------------
// CTA schedule (validated): singles get the 40 heaviest units, pairs are
// complementary -> max SM load ~16 tile-units.
// ---------------------------------------------------------------------------
__device__ __forceinline__ void sched(int bid, int& b, int& qi) {
    if (bid >= 108 && bid < 148) {
        int k = bid - 108;
        if (k < 32) { qi = 15 - (k >> 4); b = k & 15; }
        else        { qi = 13;            b = k - 32; }
    } else {
        int j = (bid < 108) ? bid : (363 - bid);
        if (j < 8) { qi = 13; b = 8 + j; }
        else       { qi = 12 - ((j - 8) >> 4); b = (j - 8) & 15; }
    }
}

// ---------------------------------------------------------------------------
// Kernel 2: fp16 mma.sync causal flash attention (R12 structure, validated
// 47.3us) + warp-uniform diagonal-tile work bounding.
// 256 threads / 8 warps; warp owns 16 q-rows; tile 128q x 128k, two 64-key
// half-phases (S -> softmax -> P(warp-private smem) -> PV), cp.async 2-buf.
// smem: K0@0 K1@18432 V0@36864 V1@55296 (each 128x72h), Ps[8][16][72]h @73728.
// ---------------------------------------------------------------------------
#define ATTN_SMEM 92160

__device__ __forceinline__ void load_kv(uint32_t sK, uint32_t sV,
                                        const uint32_t* Kg, const uint32_t* Vg,
                                        int tid) {
    #pragma unroll
    for (int p = 0; p < 4; p++) {
        int idx = tid + p * 256;          // 0..1023
        int row = idx >> 3, ch = idx & 7;
        cp16(sK + row * 144 + ch * 16, (const char*)Kg + row * 128 + ch * 16);
        cp16(sV + row * 144 + ch * 16, (const char*)Vg + row * 128 + ch * 16);
    }
}

__global__ __launch_bounds__(256, 2) void attn_kernel(float* __restrict__ out)
{
    extern __shared__ char sm[];
    const uint32_t sbase = smem_u32(sm);
    const int tid  = threadIdx.x;
    const int lane = tid & 31;
    const int g    = lane >> 2;
    const int t    = lane & 3;
    const int w    = tid >> 5;
    const int m0   = w * 16;
    int b, qi;
    sched((int)blockIdx.x, b, qi);
    const int qt0 = qi << 7;

    // kick off tile 0 loads immediately
    load_kv(sbase, sbase + 36864,
            g_Kh + (size_t)(b * NT + 0) * 32,
            g_Vh + (size_t)(b * NT + 0) * 32, tid);
    cp_commit();

    // ldmatrix per-lane base addresses (add cur*18432 for buffer)
    const uint32_t aK = sbase + ((lane & 7) + ((lane >> 4) << 3)) * 144 +
                        ((lane >> 3) & 1) * 16;
    const uint32_t aV = sbase + 36864 + (lane & 15) * 144 + (lane >> 4) * 16;
    const uint32_t aP = sbase + 73728 + w * 2304 + (lane & 15) * 144 +
                        (lane >> 4) * 16;
    __half2* PsW = (__half2*)(sm + 73728 + w * 2304);

    // Q A-fragments (already fp16 + pre-scaled in gmem)
    uint32_t qf[4][4];
    {
        const uint32_t* Qg = g_Qh + (size_t)(b * NT + qt0) * 32;
        const int r0 = m0 + g, r1 = r0 + 8;
        #pragma unroll
        for (int kc = 0; kc < 4; kc++) {
            qf[kc][0] = Qg[r0 * 32 + 8 * kc + t];
            qf[kc][1] = Qg[r1 * 32 + 8 * kc + t];
            qf[kc][2] = Qg[r0 * 32 + 8 * kc + t + 4];
            qf[kc][3] = Qg[r1 * 32 + 8 * kc + t + 4];
        }
    }

    float oacc[8][4];
    #pragma unroll
    for (int hb = 0; hb < 8; hb++)
        #pragma unroll
        for (int e = 0; e < 4; e++) oacc[hb][e] = 0.f;
    float l0 = 0.f, l1 = 0.f;

    for (int kt = 0; kt <= qi; ++kt) {
        const int cur = kt & 1;
        // prefetch next tile into the other buffer (overlaps compute below)
        if (kt < qi) {
            load_kv(sbase + (cur ^ 1) * 18432, sbase + 36864 + (cur ^ 1) * 18432,
                    g_Kh + (size_t)(b * NT + ((kt + 1) << 7)) * 32,
                    g_Vh + (size_t)(b * NT + ((kt + 1) << 7)) * 32, tid);
            cp_commit();
            cp_wait<1>();
        } else {
            cp_wait<0>();
        }
        __syncthreads();   // tile kt data visible to all warps

        const uint32_t aKc = aK + cur * 18432;
        const uint32_t aVc = aV + cur * 18432;
        const bool diag = (kt == qi);

        #pragma unroll
        for (int h = 0; h < 2; h++) {
            if (diag && h == 1 && m0 < 64) continue;   // fully masked half

            // warp-uniform chunk bound: on the diagonal tile, 16-key chunks
            // entirely above the diagonal are skipped (their elements are
            // zeroed by the mask anyway; P there is exactly 0).
            const int bnd = diag ? ((h == 0) ? (w < 4 ? w : 3) : (w - 4)) : 3;

            // ---- S = Qsc @ K^T over 64 keys ----
            float sacc[8][4];
            #pragma unroll
            for (int nb = 0; nb < 8; nb++)
                #pragma unroll
                for (int e = 0; e < 4; e++) sacc[nb][e] = 0.f;

            #pragma unroll
            for (int kc = 0; kc < 4; kc++) {
                #pragma unroll
                for (int nbp = 0; nbp < 4; nbp++) {
                    if (nbp <= bnd) {
                        uint32_t b0, b1, b2, b3;
                        ldsm4(b0, b1, b2, b3,
                              aKc + (64 * h + 16 * nbp) * 144 + kc * 32);
                        mma16(sacc[2 * nbp],     qf[kc], b0, b1);
                        mma16(sacc[2 * nbp + 1], qf[kc], b2, b3);
                    }
                }
            }

            // ---- softmax (no max-subtract), P -> warp-private smem ----
            // (skipped chunks have sacc=0 -> ex2=1, but every such element is
            //  beyond the diagonal, so the mask below zeroes it.)
            __syncwarp();   // PV of prev half done reading Ps
            const int r0 = m0 + g, r1 = r0 + 8;
            #pragma unroll
            for (int nb = 0; nb < 8; nb++) {
                const int c0 = 64 * h + 8 * nb + 2 * t;
                float e0 = ex2(sacc[nb][0]);
                float e1 = ex2(sacc[nb][1]);
                float e2 = ex2(sacc[nb][2]);
                float e3 = ex2(sacc[nb][3]);
                if (diag) {
                    if (c0     > r0) e0 = 0.f;
                    if (c0 + 1 > r0) e1 = 0.f;
                    if (c0     > r1) e2 = 0.f;
                    if (c0 + 1 > r1) e3 = 0.f;
                }
                l0 += e0 + e1;
                l1 += e2 + e3;
                uint32_t p01 = pack_h2(e0, e1), p23 = pack_h2(e2, e3);
                PsW[g * 36 + 4 * nb + t]       = *(__half2*)&p01;
                PsW[(g + 8) * 36 + 4 * nb + t] = *(__half2*)&p23;
            }
            __syncwarp();

            // ---- O += P @ V over these 64 keys (P=0 chunks skipped) ----
            #pragma unroll
            for (int kc = 0; kc < 4; kc++) {
                if (kc <= bnd) {
                    uint32_t pa[4];
                    ldsm4(pa[0], pa[1], pa[2], pa[3], aP + kc * 32);
                    #pragma unroll
                    for (int hbp = 0; hbp < 4; hbp++) {
                        uint32_t b0, b1, b2, b3;
                        ldsm4t(b0, b1, b2, b3,
                               aVc + (64 * h + 16 * kc) * 144 + hbp * 32);
                        mma16(oacc[2 * hbp],     pa, b0, b1);
                        mma16(oacc[2 * hbp + 1], pa, b2, b3);
                    }
                }
            }
        }
        __syncthreads();   // all warps done with buffer cur before refill
    }

    // ---- epilogue: reduce l across quad, normalize, store ----
    l0 += __shfl_xor_sync(0xffffffffu, l0, 1);
    l0 += __shfl_xor_sync(0xffffffffu, l0, 2);
    l1 += __shfl_xor_sync(0xffffffffu, l1, 1);
    l1 += __shfl_xor_sync(0xffffffffu, l1, 2);
    const float inv0 = 1.0f / l0;
    const float inv1 = 1.0f / l1;

    float* Og = out + (size_t)(b * NT + qt0) * HD;
    #pragma unroll
    for (int hb = 0; hb < 8; hb++) {
        int c0 = 8 * hb + 2 * t;
        *(float2*)(Og + (m0 + g) * 64 + c0) =
            make_float2(oacc[hb][0] * inv0, oacc[hb][1] * inv0);
        *(float2*)(Og + (m0 + g + 8) * 64 + c0) =
            make_float2(oacc[hb][2] * inv1, oacc[hb][3] * inv1);
    }
}

// ---------------------------------------------------------------------------
extern "C" void kernel_launch(void* const* d_in, const int* in_sizes, int n_in,
                              void* d_out, int out_size)
{
    const float* x  = (const float*)d_in[0];
    const float* Wq = (const float*)d_in[1];
    const float* Wk = (const float*)d_in[2];
    const float* Wv = (const float*)d_in[3];
    float* out = (float*)d_out;

    cudaFuncSetAttribute(qkv_kernel,  cudaFuncAttributeMaxDynamicSharedMemorySize, QKV_SMEM);
    cudaFuncSetAttribute(attn_kernel, cudaFuncAttributeMaxDynamicSharedMemorySize, ATTN_SMEM);

    qkv_kernel<<<(NB * NT) / 128, 256, QKV_SMEM>>>(x, Wq, Wk, Wv);
    attn_kernel<<<NB * (NT / 128), 256, ATTN_SMEM>>>(out);
}